// round 7
// baseline (speedup 1.0000x reference)
#include <cuda_runtime.h>
#include <cstdint>

// Beam hypotheses update — scatter, 3 slots per block for occupancy.
// Block (g, b), g in {0,1,2}, owns source slots 3g..3g+2 of row b.
// 512 threads; thread t front-loads 3 int4 (one per owned slot, addresses
// meta-independent), computes rank meta once, then 3 convert+scatter stores.
// ~40 regs -> 3 CTAs/SM (75% warp occupancy cap). No smem, no barriers.
// Output (f32, concat): len[B], worst[B], board[B,9], items[B,9,G].

#define NSLOT 9
#define SPB   3      // slots per block

__global__ __launch_bounds__(512, 3) void beam_row3_kernel(
    const int*   __restrict__ hyp,        // [B, hyp_w]
    const float* __restrict__ slp,        // [B]
    const int*   __restrict__ lnst,       // [B]
    const float* __restrict__ worst_in,   // [B]
    const float* __restrict__ board_in,   // [B, 9]
    const int*   __restrict__ items_in,   // [B, 9, 2048]
    const int*   __restrict__ curlen_ptr, // scalar (may be null)
    float*       __restrict__ out,
    int batch, int hyp_w)
{
    const int g   = blockIdx.x;           // slot group 0..2
    const int b   = blockIdx.y;           // batch row
    const int tid = threadIdx.x;          // int4 column 0..511
    const int j0  = g * SPB;

    // ---- front-batched source loads (addresses meta-independent) ----
    const int4* src_base = reinterpret_cast<const int4*>(
        items_in + (size_t)b * NSLOT * 2048);
    int4 a[SPB];
#pragma unroll
    for (int s = 0; s < SPB; s++)
        a[s] = __ldcs(&src_base[(j0 + s) * 512 + tid]);

    // ---- meta (once per thread) ----
    const int cur_len   = curlen_ptr ? __ldg(curlen_ptr) : hyp_w;
    const int num_beams = NSLOT - 1;

    const float score = __ldg(&slp[b]) / (float)cur_len;   // length_penalty=1
    const int   ln    = __ldg(&lnst[b]);
    const float worst = __ldg(&worst_in[b]);
    const bool  cond  = (ln < num_beams) || (score > worst);
    const int   new_len = ln + 1;
    const int   ins_idx = (new_len > NSLOT) ? 0 : num_beams;

    float v[NSLOT];
    float bins[SPB];                      // original board values, owned slots
#pragma unroll
    for (int i = 0; i < NSLOT; i++) {
        float bi = __ldg(&board_in[(size_t)b * NSLOT + i]);
#pragma unroll
        for (int s = 0; s < SPB; s++)
            if (i == j0 + s) bins[s] = bi;
        v[i] = (i == ins_idx) ? score : bi;
    }

    // dest for each owned slot = stable rank of (v[j], j)
    int dest[SPB];
#pragma unroll
    for (int s = 0; s < SPB; s++) {
        const int j = j0 + s;
        int r = 0;
#pragma unroll
        for (int k = 0; k < NSLOT; k++)
            if (k != j)
                r += ((v[k] < v[j]) || (v[k] == v[j] && k < j)) ? 1 : 0;
        dest[s] = cond ? r : j;
    }

    // ---- scalar outputs ----
    if (tid == 0) {
        float* ob = out + (size_t)2 * batch + (size_t)b * NSLOT;
#pragma unroll
        for (int s = 0; s < SPB; s++)
            ob[dest[s]] = cond ? v[j0 + s] : bins[s];

        if (g == 0) {
            out[b] = (float)(cond ? new_len : ln);
            // second smallest by (value, index)
            float m1 = v[0]; int m1i = 0;
#pragma unroll
            for (int i = 1; i < NSLOT; i++)
                if (v[i] < m1) { m1 = v[i]; m1i = i; }
            float m2 = 3.402823466e+38f;
#pragma unroll
            for (int i = 0; i < NSLOT; i++)
                if (i != m1i) m2 = fminf(m2, v[i]);
            const float new_worst =
                (new_len > num_beams) ? m2 : fminf(worst, score);
            out[batch + b] = cond ? new_worst : worst;
        }
    }

    // ---- hyp overlay on the replaced slot (first cur_len elements) ----
    if (cond && ins_idx >= j0 && ins_idx < j0 + SPB) {
        const int* h = hyp + (size_t)b * hyp_w;
        if ((cur_len & 3) == 0 && (hyp_w & 3) == 0) {
            if (tid < (cur_len >> 2)) {
                int4 hv = __ldg(&reinterpret_cast<const int4*>(h)[tid]);
#pragma unroll
                for (int s = 0; s < SPB; s++)
                    if (j0 + s == ins_idx) a[s] = hv;
            }
        } else {
            int base = tid << 2;
            if (base < cur_len) {
#pragma unroll
                for (int s = 0; s < SPB; s++)
                    if (j0 + s == ins_idx) {
                        if (base + 0 < cur_len) a[s].x = h[base + 0];
                        if (base + 1 < cur_len) a[s].y = h[base + 1];
                        if (base + 2 < cur_len) a[s].z = h[base + 2];
                        if (base + 3 < cur_len) a[s].w = h[base + 3];
                    }
            }
        }
    }

    // ---- convert + scatter stores ----
    float4* dst_base = reinterpret_cast<float4*>(
        out + (size_t)batch * (2 + NSLOT) + (size_t)b * NSLOT * 2048);
#pragma unroll
    for (int s = 0; s < SPB; s++) {
        float4 f;
        f.x = (float)a[s].x; f.y = (float)a[s].y;
        f.z = (float)a[s].z; f.w = (float)a[s].w;
        __stcs(&dst_base[dest[s] * 512 + tid], f);
    }
}

// ---------------- generic fallback (arbitrary gen_len), per-slot grid ------
__global__ __launch_bounds__(128) void beam_scatter_kernel_gen(
    const int*   __restrict__ hyp,
    const float* __restrict__ slp,
    const int*   __restrict__ lnst,
    const float* __restrict__ worst_in,
    const float* __restrict__ board_in,
    const int*   __restrict__ items_in,
    const int*   __restrict__ curlen_ptr,
    float*       __restrict__ out,
    int batch, int hyp_w, int gen_len)
{
    const int j   = blockIdx.x;
    const int b   = blockIdx.y;
    const int tid = threadIdx.x;

    const int cur_len   = curlen_ptr ? __ldg(curlen_ptr) : hyp_w;
    const int num_beams = NSLOT - 1;

    const float score = __ldg(&slp[b]) / (float)cur_len;
    const int   ln    = __ldg(&lnst[b]);
    const float worst = __ldg(&worst_in[b]);
    const bool  cond  = (ln < num_beams) || (score > worst);
    const int   new_len = ln + 1;
    const int   ins_idx = (new_len > NSLOT) ? 0 : num_beams;

    float v[NSLOT];
    float binj = 0.f;
#pragma unroll
    for (int i = 0; i < NSLOT; i++) {
        v[i] = __ldg(&board_in[(size_t)b * NSLOT + i]);
        if (i == j) binj = v[i];
    }
#pragma unroll
    for (int i = 0; i < NSLOT; i++)
        if (i == ins_idx) v[i] = score;

    int r = 0;
#pragma unroll
    for (int k = 0; k < NSLOT; k++)
        if (k != j)
            r += ((v[k] < v[j]) || (v[k] == v[j] && k < j)) ? 1 : 0;

    const int  dest    = cond ? r : j;
    const bool use_hyp = cond && (j == ins_idx);

    if (tid == 0) {
        out[(size_t)2 * batch + (size_t)b * NSLOT + dest] = cond ? v[j] : binj;
        if (j == 0) {
            float m1 = v[0]; int m1i = 0;
#pragma unroll
            for (int i = 1; i < NSLOT; i++)
                if (v[i] < m1) { m1 = v[i]; m1i = i; }
            float m2 = 3.402823466e+38f;
#pragma unroll
            for (int i = 0; i < NSLOT; i++)
                if (i != m1i) m2 = fminf(m2, v[i]);
            const float new_worst =
                (new_len > num_beams) ? m2 : fminf(worst, score);
            out[b]         = (float)(cond ? new_len : ln);
            out[batch + b] = cond ? new_worst : worst;
        }
    }

    const int* src_row = items_in + ((size_t)b * NSLOT + j) * gen_len;
    float*     dst_row = out + (size_t)batch * (2 + NSLOT) +
                         ((size_t)b * NSLOT + dest) * gen_len;
    const int* h = hyp + (size_t)b * hyp_w;

    for (int e = tid; e < gen_len; e += 128) {
        int val = (use_hyp && e < cur_len) ? h[e] : __ldcs(&src_row[e]);
        __stcs(&dst_row[e], (float)val);
    }
}

extern "C" void kernel_launch(void* const* d_in, const int* in_sizes, int n_in,
                              void* d_out, int out_size)
{
    const int*   hyp    = (const int*)  d_in[0];
    const float* slp    = (const float*)d_in[1];
    const int*   lnst   = (const int*)  d_in[2];
    const float* worst  = (const float*)d_in[3];
    const float* board  = (const float*)d_in[4];
    const int*   items  = (const int*)  d_in[5];
    const int*   curlen = (n_in > 6) ? (const int*)d_in[6] : nullptr;

    const int batch   = in_sizes[1];
    const int hyp_w   = in_sizes[0] / batch;
    const int gen_len = in_sizes[5] / (batch * NSLOT);
    float* out = (float*)d_out;

    if (gen_len == 2048) {
        dim3 grid(3, batch);
        beam_row3_kernel<<<grid, 512>>>(
            hyp, slp, lnst, worst, board, items, curlen, out,
            batch, hyp_w);
    } else {
        dim3 grid(NSLOT, batch);
        beam_scatter_kernel_gen<<<grid, 128>>>(
            hyp, slp, lnst, worst, board, items, curlen, out,
            batch, hyp_w, gen_len);
    }
}

// round 9
// speedup vs baseline: 1.1356x; 1.1356x over previous
#include <cuda_runtime.h>
#include <cstdint>

// Beam hypotheses update — scatter kernel, warp-0 meta.
// Block (j, b): all 128 threads front-issue 4 int4 loads of SOURCE row j
// (address meta-independent, in flight immediately). Warp 0 alone computes
// the rank meta (dest slot, use_hyp) and scalar outputs, publishes via smem.
// __syncthreads gates only the stores. Loads overlap meta fully.
// Output (f32, concat): len[B], worst[B], board[B,9], items[B,9,G].

#define NSLOT 9

template <int VPT>
__global__ __launch_bounds__(128) void beam_scatter_w0_kernel(
    const int*   __restrict__ hyp,        // [B, hyp_w]
    const float* __restrict__ slp,        // [B]
    const int*   __restrict__ lnst,       // [B]
    const float* __restrict__ worst_in,   // [B]
    const float* __restrict__ board_in,   // [B, 9]
    const int*   __restrict__ items_in,   // [B, 9, G]
    const int*   __restrict__ curlen_ptr, // scalar (may be null)
    float*       __restrict__ out,
    int batch, int hyp_w, int gen_len)
{
    const int j   = blockIdx.x;           // SOURCE slot 0..8
    const int b   = blockIdx.y;           // batch row
    const int tid = threadIdx.x;

    __shared__ int s_code;                // low bits: dest; bit30: use_hyp

    // ---- front-batched source loads: issue before any meta work ----
    const int4* src_row = reinterpret_cast<const int4*>(
        items_in + ((size_t)b * NSLOT + j) * gen_len);
    int4 a[VPT];
#pragma unroll
    for (int it = 0; it < VPT; it++)
        a[it] = __ldcs(&src_row[tid + it * 128]);

    const int cur_len = curlen_ptr ? __ldg(curlen_ptr) : hyp_w;

    // ---- meta: warp 0 only (redundant per lane; lane 0 writes) ----
    if (tid < 32) {
        const int num_beams = NSLOT - 1;
        const float score = __ldg(&slp[b]) / (float)cur_len;  // len_pen = 1
        const int   ln    = __ldg(&lnst[b]);
        const float worst = __ldg(&worst_in[b]);
        const bool  cond  = (ln < num_beams) || (score > worst);
        const int   new_len = ln + 1;
        const int   ins_idx = (new_len > NSLOT) ? 0 : num_beams;

        float v[NSLOT];
        float binj = 0.f;
#pragma unroll
        for (int i = 0; i < NSLOT; i++) {
            v[i] = __ldg(&board_in[(size_t)b * NSLOT + i]);
            if (i == j) binj = v[i];
        }
#pragma unroll
        for (int i = 0; i < NSLOT; i++)
            if (i == ins_idx) v[i] = score;

        // stable rank of (v[j], j) ascending
        int r = 0;
#pragma unroll
        for (int k = 0; k < NSLOT; k++)
            if (k != j)
                r += ((v[k] < v[j]) || (v[k] == v[j] && k < j)) ? 1 : 0;

        const int dest = cond ? r : j;

        if (tid == 0) {
            s_code = dest | ((cond && j == ins_idx) ? 0x40000000 : 0);
            out[(size_t)2 * batch + (size_t)b * NSLOT + dest] =
                cond ? v[j] : binj;
            if (j == 0) {
                // second smallest by (value, index)
                float m1 = v[0]; int m1i = 0;
#pragma unroll
                for (int i = 1; i < NSLOT; i++)
                    if (v[i] < m1) { m1 = v[i]; m1i = i; }
                float m2 = 3.402823466e+38f;
#pragma unroll
                for (int i = 0; i < NSLOT; i++)
                    if (i != m1i) m2 = fminf(m2, v[i]);
                const float new_worst =
                    (new_len > num_beams) ? m2 : fminf(worst, score);
                out[b]         = (float)(cond ? new_len : ln);
                out[batch + b] = cond ? new_worst : worst;
            }
        }
    }
    __syncthreads();

    const int  code    = s_code;
    const int  dest    = code & 0xFFFF;
    const bool use_hyp = (code & 0x40000000) != 0;

    // ---- hyp overlay (only the replaced source row; first cur_len elems) ----
    if (use_hyp) {
        const int* h = hyp + (size_t)b * hyp_w;
        if ((cur_len & 3) == 0 && (hyp_w & 3) == 0) {
            const int4* hyp_row = reinterpret_cast<const int4*>(h);
            const int cvec = cur_len >> 2;
#pragma unroll
            for (int it = 0; it < VPT; it++) {
                int vix = tid + it * 128;
                if (vix < cvec) a[it] = __ldg(&hyp_row[vix]);
            }
        } else {
#pragma unroll
            for (int it = 0; it < VPT; it++) {
                int base = (tid + it * 128) << 2;
                if (base + 0 < cur_len) a[it].x = h[base + 0];
                if (base + 1 < cur_len) a[it].y = h[base + 1];
                if (base + 2 < cur_len) a[it].z = h[base + 2];
                if (base + 3 < cur_len) a[it].w = h[base + 3];
            }
        }
    }

    // ---- convert + scatter stores ----
    float4* dst_row = reinterpret_cast<float4*>(
        out + (size_t)batch * (2 + NSLOT) +
        ((size_t)b * NSLOT + dest) * gen_len);
#pragma unroll
    for (int it = 0; it < VPT; it++) {
        float4 f;
        f.x = (float)a[it].x; f.y = (float)a[it].y;
        f.z = (float)a[it].z; f.w = (float)a[it].w;
        __stcs(&dst_row[tid + it * 128], f);
    }
}

// ---------------- generic fallback (arbitrary gen_len) ---------------------
__global__ __launch_bounds__(128) void beam_scatter_kernel_gen(
    const int*   __restrict__ hyp,
    const float* __restrict__ slp,
    const int*   __restrict__ lnst,
    const float* __restrict__ worst_in,
    const float* __restrict__ board_in,
    const int*   __restrict__ items_in,
    const int*   __restrict__ curlen_ptr,
    float*       __restrict__ out,
    int batch, int hyp_w, int gen_len)
{
    const int j   = blockIdx.x;
    const int b   = blockIdx.y;
    const int tid = threadIdx.x;

    const int cur_len   = curlen_ptr ? __ldg(curlen_ptr) : hyp_w;
    const int num_beams = NSLOT - 1;

    const float score = __ldg(&slp[b]) / (float)cur_len;
    const int   ln    = __ldg(&lnst[b]);
    const float worst = __ldg(&worst_in[b]);
    const bool  cond  = (ln < num_beams) || (score > worst);
    const int   new_len = ln + 1;
    const int   ins_idx = (new_len > NSLOT) ? 0 : num_beams;

    float v[NSLOT];
    float binj = 0.f;
#pragma unroll
    for (int i = 0; i < NSLOT; i++) {
        v[i] = __ldg(&board_in[(size_t)b * NSLOT + i]);
        if (i == j) binj = v[i];
    }
#pragma unroll
    for (int i = 0; i < NSLOT; i++)
        if (i == ins_idx) v[i] = score;

    int r = 0;
#pragma unroll
    for (int k = 0; k < NSLOT; k++)
        if (k != j)
            r += ((v[k] < v[j]) || (v[k] == v[j] && k < j)) ? 1 : 0;

    const int  dest    = cond ? r : j;
    const bool use_hyp = cond && (j == ins_idx);

    if (tid == 0) {
        out[(size_t)2 * batch + (size_t)b * NSLOT + dest] = cond ? v[j] : binj;
        if (j == 0) {
            float m1 = v[0]; int m1i = 0;
#pragma unroll
            for (int i = 1; i < NSLOT; i++)
                if (v[i] < m1) { m1 = v[i]; m1i = i; }
            float m2 = 3.402823466e+38f;
#pragma unroll
            for (int i = 0; i < NSLOT; i++)
                if (i != m1i) m2 = fminf(m2, v[i]);
            const float new_worst =
                (new_len > num_beams) ? m2 : fminf(worst, score);
            out[b]         = (float)(cond ? new_len : ln);
            out[batch + b] = cond ? new_worst : worst;
        }
    }

    const int* src_row = items_in + ((size_t)b * NSLOT + j) * gen_len;
    float*     dst_row = out + (size_t)batch * (2 + NSLOT) +
                         ((size_t)b * NSLOT + dest) * gen_len;
    const int* h = hyp + (size_t)b * hyp_w;

    for (int e = tid; e < gen_len; e += 128) {
        int val = (use_hyp && e < cur_len) ? h[e] : __ldcs(&src_row[e]);
        __stcs(&dst_row[e], (float)val);
    }
}

extern "C" void kernel_launch(void* const* d_in, const int* in_sizes, int n_in,
                              void* d_out, int out_size)
{
    const int*   hyp    = (const int*)  d_in[0];
    const float* slp    = (const float*)d_in[1];
    const int*   lnst   = (const int*)  d_in[2];
    const float* worst  = (const float*)d_in[3];
    const float* board  = (const float*)d_in[4];
    const int*   items  = (const int*)  d_in[5];
    const int*   curlen = (n_in > 6) ? (const int*)d_in[6] : nullptr;

    const int batch   = in_sizes[1];
    const int hyp_w   = in_sizes[0] / batch;
    const int gen_len = in_sizes[5] / (batch * NSLOT);
    float* out = (float*)d_out;

    dim3 grid(NSLOT, batch);
    if (gen_len == 2048) {
        beam_scatter_w0_kernel<4><<<grid, 128>>>(
            hyp, slp, lnst, worst, board, items, curlen, out,
            batch, hyp_w, gen_len);
    } else {
        beam_scatter_kernel_gen<<<grid, 128>>>(
            hyp, slp, lnst, worst, board, items, curlen, out,
            batch, hyp_w, gen_len);
    }
}